// round 3
// baseline (speedup 1.0000x reference)
#include <cuda_runtime.h>
#include <cuda_bf16.h>
#include <math.h>

#ifndef M_PI
#define M_PI 3.14159265358979323846
#endif

// ---------------- constants ----------------
#define BATCH 1024
#define NCH 32
#define LIN 1024
#define LCONV 1041   // conv output length (pad 16,16, k=16)
#define LH 520       // after avgpool(3,2)
#define L1 257       // after stage1 window(8,2)
#define L2 125       // after stage2 window(8,2)
#define LM 31        // after maxpool(4,4)
#define LE 12        // after final eventually
#define XPAD 1056    // padded signal length (16 + 1024 + 16)

// ---------------- device scratch (static; no runtime allocation) ----------------
__device__ float g_filt[NCH * 16];
__device__ float g_wbar[NCH * 18];            // fused conv16+avgpool3/2 stride-2 taps (incl /3)
__device__ float g_p1sum[NCH * BATCH];
__device__ float g_p1sq[NCH * BATCH];
__device__ float g_bn1s[NCH];
__device__ float g_bn1t[NCH];
__device__ float g_h[BATCH * NCH * LH];       // pooled+BN'd features
__device__ float g_m1[BATCH * NCH * LM];      // branch1 maxpool out
__device__ float g_m2[BATCH * NCH * LM];      // branch2 maxpool out
__device__ float g_p2sum[2 * NCH * BATCH];
__device__ float g_p2sq[2 * NCH * BATCH];
__device__ float g_eff[2 * NCH * 2];          // (alpha, beta) per (branch, channel)
__device__ float g_z[BATCH * 768];
__device__ float g_h1[BATCH * 1024];
__device__ float g_h2[BATCH * 512];
__device__ float g_h3[BATCH * 128];

// ---------------- K0: Laplace filters + fused 18-tap weights ----------------
__global__ void k_setup(const float* __restrict__ la_a, const float* __restrict__ la_b) {
    __shared__ float sf[NCH * 16];
    int t = threadIdx.x; // 512 threads
    {
        int c = t >> 4, k = t & 15;
        double tt = (double)k / 15.0;
        double p = tt - (double)la_b[c] / (double)la_a[c];
        double arg = 2.0 * M_PI * 50.0 * (p - 0.1);
        double coeff = 0.03 / sqrt(1.0 - 0.03 * 0.03);
        double y = 0.08 * exp(-coeff * arg) * (-sin(arg));
        sf[t] = (float)y;
        g_filt[t] = (float)y;
    }
    __syncthreads();
    for (int i = t; i < NCH * 18; i += 512) {
        int c = i / 18, j = i % 18;
        float s = 0.f;
        #pragma unroll
        for (int d = 0; d < 3; ++d) {
            int k = j - d;
            if (k >= 0 && k < 16) s += sf[c * 16 + k];
        }
        g_wbar[i] = s * (1.0f / 3.0f);
    }
}

// ---------------- K1: per-(b,c) conv sum & sumsq partials ----------------
__global__ void __launch_bounds__(256) k_stats1(const float* __restrict__ x) {
    __shared__ float xp[XPAD];
    int b = blockIdx.x, t = threadIdx.x;
    for (int j = t; j < XPAD; j += 256)
        xp[j] = (j >= 16 && j < 16 + LIN) ? x[b * LIN + (j - 16)] : 0.f;
    __syncthreads();
    int w = t >> 5, lane = t & 31;
    for (int c = w; c < NCH; c += 8) {
        float f[16];
        #pragma unroll
        for (int k = 0; k < 16; ++k) f[k] = g_filt[c * 16 + k];
        float s = 0.f, q = 0.f;
        for (int l = lane; l < LCONV; l += 32) {
            float v = 0.f;
            #pragma unroll
            for (int k = 0; k < 16; ++k) v += f[k] * xp[l + k];
            s += v;
            q += v * v;
        }
        #pragma unroll
        for (int o = 16; o > 0; o >>= 1) {
            s += __shfl_down_sync(0xffffffffu, s, o);
            q += __shfl_down_sync(0xffffffffu, q, o);
        }
        if (lane == 0) {
            g_p1sum[c * BATCH + b] = s;
            g_p1sq[c * BATCH + b] = q;
        }
    }
}

// ---------------- K2: BN1 affine params (double reduce) ----------------
__global__ void __launch_bounds__(256) k_bn1(const float* __restrict__ bn1_g,
                                             const float* __restrict__ bn1_b) {
    int c = blockIdx.x, t = threadIdx.x;
    double s = 0.0, q = 0.0;
    for (int b = t; b < BATCH; b += 256) {
        s += (double)g_p1sum[c * BATCH + b];
        q += (double)g_p1sq[c * BATCH + b];
    }
    __shared__ double rs[8], rq[8];
    int lane = t & 31, w = t >> 5;
    #pragma unroll
    for (int o = 16; o > 0; o >>= 1) {
        s += __shfl_down_sync(0xffffffffu, s, o);
        q += __shfl_down_sync(0xffffffffu, q, o);
    }
    if (lane == 0) { rs[w] = s; rq[w] = q; }
    __syncthreads();
    if (t == 0) {
        double S = 0.0, Q = 0.0;
        #pragma unroll
        for (int i = 0; i < 8; ++i) { S += rs[i]; Q += rq[i]; }
        double N = (double)BATCH * (double)LCONV;
        double mean = S / N;
        double var = Q / N - mean * mean;
        double sc = (double)bn1_g[c] / sqrt(var + 1e-5);
        g_bn1s[c] = (float)sc;
        g_bn1t[c] = (float)((double)bn1_b[c] - sc * mean);
    }
}

// ---------------- K3: fused conv+avgpool+BN -> g_h ----------------
__global__ void __launch_bounds__(256) k_h(const float* __restrict__ x) {
    __shared__ float xp[XPAD];
    int b = blockIdx.x, t = threadIdx.x;
    for (int j = t; j < XPAD; j += 256)
        xp[j] = (j >= 16 && j < 16 + LIN) ? x[b * LIN + (j - 16)] : 0.f;
    __syncthreads();
    int w = t >> 5, lane = t & 31;
    for (int c = w; c < NCH; c += 8) {
        float wb[18];
        #pragma unroll
        for (int j = 0; j < 18; ++j) wb[j] = g_wbar[c * 18 + j];
        float sc = g_bn1s[c], sh = g_bn1t[c];
        float* hout = g_h + ((long)b * NCH + c) * LH;
        for (int n = lane; n < LH; n += 32) {
            float v = 0.f;
            #pragma unroll
            for (int j = 0; j < 18; ++j) v += wb[j] * xp[2 * n + j];
            hout[n] = sc * v + sh;
        }
    }
}

// ---------------- K4: both branch pipelines (warp per channel) ----------------
__global__ void __launch_bounds__(128) k_branch(
    const float* __restrict__ a1_w, const float* __restrict__ a1_b,
    const float* __restrict__ e1_w, const float* __restrict__ e1_b,
    const float* __restrict__ f1_w, const float* __restrict__ f1_b,
    const float* __restrict__ fa_w, const float* __restrict__ fa_b) {
    __shared__ float sh[4][LH];
    __shared__ float s1[4][264];
    __shared__ float s2[4][128];
    int b = blockIdx.x;
    int t = threadIdx.x, w = t >> 5, lane = t & 31;
    int c = blockIdx.y * 4 + w;
    const float* hin = g_h + ((long)b * NCH + c) * LH;
    for (int i = lane; i < LH; i += 32) sh[w][i] = hin[i];
    __syncwarp();
    #pragma unroll
    for (int br = 0; br < 2; ++br) {
        const float* w1p = (br == 0) ? a1_w : f1_w;
        const float* b1p = (br == 0) ? a1_b : f1_b;
        const float* w2p = (br == 0) ? e1_w : fa_w;
        const float* b2p = (br == 0) ? e1_b : fa_b;
        float wa[8], wbv[8], sa = 0.f, sb2 = 0.f;
        #pragma unroll
        for (int k = 0; k < 8; ++k) {
            wa[k] = w1p[c * 8 + k]; sa += wa[k];
            wbv[k] = w2p[c * 8 + k]; sb2 += wbv[k];
        }
        // branch0: stage1 = always, stage2 = eventually.  branch1: swapped.
        float beff1 = (br == 0) ? (b1p[c] - sa) : (1.f - b1p[c]);
        float beff2 = (br == 0) ? (1.f - b2p[c]) : (b2p[c] - sb2);
        for (int n = lane; n < L1; n += 32) {
            float d = beff1;
            #pragma unroll
            for (int k = 0; k < 8; ++k) d += sh[w][2 * n + k] * wa[k];
            s1[w][n] = d > 0.f ? d : 0.f;
        }
        __syncwarp();
        for (int n = lane; n < L2; n += 32) {
            float d = beff2;
            #pragma unroll
            for (int k = 0; k < 8; ++k) d += s1[w][2 * n + k] * wbv[k];
            s2[w][n] = d > 0.f ? d : 0.f;
        }
        __syncwarp();
        float mv = 0.f;
        if (lane < LM) {
            mv = s2[w][4 * lane];
            #pragma unroll
            for (int j = 1; j < 4; ++j) mv = fmaxf(mv, s2[w][4 * lane + j]);
            float* mo = (br == 0 ? g_m1 : g_m2) + ((long)b * NCH + c) * LM;
            mo[lane] = mv;
        }
        float s = (lane < LM) ? mv : 0.f;
        float q = s * mv; // 0 for lane>=LM
        #pragma unroll
        for (int o = 16; o > 0; o >>= 1) {
            s += __shfl_down_sync(0xffffffffu, s, o);
            q += __shfl_down_sync(0xffffffffu, q, o);
        }
        if (lane == 0) {
            g_p2sum[(br * NCH + c) * BATCH + b] = s;
            g_p2sq[(br * NCH + c) * BATCH + b] = q;
        }
        __syncwarp();
    }
}

// ---------------- K5: BN2/BN3 params folded into final eventually ----------------
__global__ void __launch_bounds__(256) k_bn23(
    const float* __restrict__ bn2_g, const float* __restrict__ bn2_b,
    const float* __restrict__ e2_w, const float* __restrict__ e2_b,
    const float* __restrict__ bn3_g, const float* __restrict__ bn3_b,
    const float* __restrict__ f2_w, const float* __restrict__ f2_b) {
    int idx = blockIdx.x;  // br*32 + c
    int br = idx >> 5, c = idx & 31;
    int t = threadIdx.x;
    double s = 0.0, q = 0.0;
    for (int b = t; b < BATCH; b += 256) {
        s += (double)g_p2sum[idx * BATCH + b];
        q += (double)g_p2sq[idx * BATCH + b];
    }
    __shared__ double rs[8], rq[8];
    int lane = t & 31, w = t >> 5;
    #pragma unroll
    for (int o = 16; o > 0; o >>= 1) {
        s += __shfl_down_sync(0xffffffffu, s, o);
        q += __shfl_down_sync(0xffffffffu, q, o);
    }
    if (lane == 0) { rs[w] = s; rq[w] = q; }
    __syncthreads();
    if (t == 0) {
        double S = 0.0, Q = 0.0;
        #pragma unroll
        for (int i = 0; i < 8; ++i) { S += rs[i]; Q += rq[i]; }
        double N = (double)BATCH * (double)LM;
        double mean = S / N;
        double var = Q / N - mean * mean;
        const float* gg = br ? bn3_g : bn2_g;
        const float* gb = br ? bn3_b : bn2_b;
        const float* wp = br ? f2_w : e2_w;
        const float* bp = br ? f2_b : e2_b;
        double sc = (double)gg[c] / sqrt(var + 1e-5);
        double tt = (double)gb[c] - sc * mean;
        double sumw = 0.0;
        for (int k = 0; k < 8; ++k) sumw += (double)wp[c * 8 + k];
        // eventually on (sc*m + tt): r = (1 - b + tt*sumw) + sc * dot(m_win, w)
        g_eff[idx * 2 + 0] = (float)sc;
        g_eff[idx * 2 + 1] = (float)(1.0 - (double)bp[c] + tt * sumw);
    }
}

// ---------------- K6: final eventually layers + concat -> g_z ----------------
__global__ void __launch_bounds__(256) k_e2z(const float* __restrict__ e2_w,
                                             const float* __restrict__ f2_w) {
    __shared__ float sm[2 * NCH * LM]; // 1984
    int b = blockIdx.x, t = threadIdx.x;
    for (int i = t; i < NCH * LM; i += 256) {
        sm[i] = g_m1[(long)b * NCH * LM + i];
        sm[NCH * LM + i] = g_m2[(long)b * NCH * LM + i];
    }
    __syncthreads();
    #pragma unroll
    for (int r = 0; r < 3; ++r) {
        int o = t + 256 * r;           // 0..767
        int br = o / 384;
        int rem = o - br * 384;
        int c = rem / LE, n = rem - c * LE;
        const float* wp = br ? f2_w : e2_w;
        float alpha = g_eff[(br * NCH + c) * 2 + 0];
        float beta  = g_eff[(br * NCH + c) * 2 + 1];
        const float* m = sm + br * (NCH * LM) + c * LM + 2 * n;
        float d = 0.f;
        #pragma unroll
        for (int k = 0; k < 8; ++k) d += m[k] * wp[c * 8 + k];
        float v = beta + alpha * d;
        g_z[(long)b * 768 + o] = v > 0.f ? v : 0.f;
    }
}

// ---------------- tiled fp32 GEMM: C = relu(A@W + bias) ----------------
// A (M,K) row-major, W (K,N) row-major, all dims multiples of 64 / K of 8.
__global__ void __launch_bounds__(256) k_gemm_relu(
    const float* __restrict__ A, const float* __restrict__ W,
    const float* __restrict__ bias, float* __restrict__ C,
    int M, int N, int K) {
    __shared__ float As[8][64];
    __shared__ float Ws[8][64];
    int tid = threadIdx.x;
    int tx = tid & 15, ty = tid >> 4;
    int row0 = blockIdx.y * 64, col0 = blockIdx.x * 64;
    float acc[4][4] = {};
    for (int k0 = 0; k0 < K; k0 += 8) {
        #pragma unroll
        for (int i = 0; i < 2; ++i) {
            int e = tid + 256 * i;
            int r = e >> 3, kk = e & 7;
            As[kk][r] = A[(long)(row0 + r) * K + k0 + kk];
        }
        #pragma unroll
        for (int i = 0; i < 2; ++i) {
            int e = tid + 256 * i;
            int kk = e >> 6, n = e & 63;
            Ws[kk][n] = W[(long)(k0 + kk) * N + col0 + n];
        }
        __syncthreads();
        #pragma unroll
        for (int kk = 0; kk < 8; ++kk) {
            float a[4], wv[4];
            *(float4*)a = *(const float4*)&As[kk][ty * 4];
            *(float4*)wv = *(const float4*)&Ws[kk][tx * 4];
            #pragma unroll
            for (int i = 0; i < 4; ++i)
                #pragma unroll
                for (int j = 0; j < 4; ++j) acc[i][j] += a[i] * wv[j];
        }
        __syncthreads();
    }
    #pragma unroll
    for (int i = 0; i < 4; ++i) {
        int m = row0 + ty * 4 + i;
        #pragma unroll
        for (int j = 0; j < 4; ++j) {
            int n = col0 + tx * 4 + j;
            float v = acc[i][j] + bias[n];
            C[(long)m * N + n] = v > 0.f ? v : 0.f;
        }
    }
}

// ---------------- final 128->10 layer ----------------
__global__ void __launch_bounds__(256) k_fc4(const float* __restrict__ w4,
                                             const float* __restrict__ b4,
                                             float* __restrict__ out) {
    int g = blockIdx.x * 256 + threadIdx.x;
    if (g >= BATCH * 10) return;
    int b = g / 10, j = g - b * 10;
    const float* h = g_h3 + (long)b * 128;
    float acc = b4[j];
    #pragma unroll 16
    for (int k = 0; k < 128; ++k) acc += h[k] * w4[k * 10 + j];
    out[g] = acc > 0.f ? acc : 0.f;
}

// ---------------- launcher ----------------
extern "C" void kernel_launch(void* const* d_in, const int* in_sizes, int n_in,
                              void* d_out, int out_size) {
    (void)in_sizes; (void)n_in; (void)out_size;
    const float* x      = (const float*)d_in[0];
    const float* la_a   = (const float*)d_in[1];
    const float* la_b   = (const float*)d_in[2];
    // d_in[3] la_bias: cancels under BN1 (constant per channel) -> unused
    const float* bn1_g  = (const float*)d_in[4];
    const float* bn1_b  = (const float*)d_in[5];
    const float* a1_w   = (const float*)d_in[6];
    const float* a1_b   = (const float*)d_in[7];
    const float* e1_w   = (const float*)d_in[8];
    const float* e1_b   = (const float*)d_in[9];
    const float* bn2_g  = (const float*)d_in[10];
    const float* bn2_b  = (const float*)d_in[11];
    const float* e2_w   = (const float*)d_in[12];
    const float* e2_b   = (const float*)d_in[13];
    const float* f1_w   = (const float*)d_in[14];
    const float* f1_b   = (const float*)d_in[15];
    const float* fa_w   = (const float*)d_in[16];
    const float* fa_b   = (const float*)d_in[17];
    const float* bn3_g  = (const float*)d_in[18];
    const float* bn3_b  = (const float*)d_in[19];
    const float* f2_w   = (const float*)d_in[20];
    const float* f2_b   = (const float*)d_in[21];
    const float* w1     = (const float*)d_in[22];
    const float* b1     = (const float*)d_in[23];
    const float* w2     = (const float*)d_in[24];
    const float* b2     = (const float*)d_in[25];
    const float* w3     = (const float*)d_in[26];
    const float* b3     = (const float*)d_in[27];
    const float* w4     = (const float*)d_in[28];
    const float* b4     = (const float*)d_in[29];
    float* out = (float*)d_out;

    float *p_z, *p_h1, *p_h2;
    cudaGetSymbolAddress((void**)&p_z, g_z);
    cudaGetSymbolAddress((void**)&p_h1, g_h1);
    cudaGetSymbolAddress((void**)&p_h2, g_h2);
    float *p_h3;
    cudaGetSymbolAddress((void**)&p_h3, g_h3);

    k_setup<<<1, 512>>>(la_a, la_b);
    k_stats1<<<BATCH, 256>>>(x);
    k_bn1<<<NCH, 256>>>(bn1_g, bn1_b);
    k_h<<<BATCH, 256>>>(x);
    k_branch<<<dim3(BATCH, 8), 128>>>(a1_w, a1_b, e1_w, e1_b, f1_w, f1_b, fa_w, fa_b);
    k_bn23<<<64, 256>>>(bn2_g, bn2_b, e2_w, e2_b, bn3_g, bn3_b, f2_w, f2_b);
    k_e2z<<<BATCH, 256>>>(e2_w, f2_w);
    k_gemm_relu<<<dim3(1024 / 64, BATCH / 64), 256>>>(p_z, w1, b1, p_h1, BATCH, 1024, 768);
    k_gemm_relu<<<dim3(512 / 64, BATCH / 64), 256>>>(p_h1, w2, b2, p_h2, BATCH, 512, 1024);
    k_gemm_relu<<<dim3(128 / 64, BATCH / 64), 256>>>(p_h2, w3, b3, p_h3, BATCH, 128, 512);
    k_fc4<<<(BATCH * 10 + 255) / 256, 256>>>(w4, b4, out);
}

// round 4
// speedup vs baseline: 1.4048x; 1.4048x over previous
#include <cuda_runtime.h>
#include <cuda_bf16.h>
#include <math.h>

#ifndef M_PI
#define M_PI 3.14159265358979323846
#endif

// ---------------- constants ----------------
#define BATCH 1024
#define NCH 32
#define LIN 1024
#define LCONV 1041
#define LH 520
#define L1 257
#define L2 125
#define LM 31
#define LE 12

// ---------------- device scratch ----------------
__device__ float g_filt[NCH * 16];
__device__ float g_wbar[NCH * 18];
__device__ float g_stats1[BATCH * 17];      // per b: [Sx, C(0..15)]
__device__ float g_bn1s[NCH];
__device__ float g_bn1t[NCH];
__device__ float g_m1[BATCH * NCH * LM];
__device__ float g_m2[BATCH * NCH * LM];
__device__ float g_p2sum[2 * NCH * BATCH];
__device__ float g_p2sq[2 * NCH * BATCH];
__device__ float g_eff[2 * NCH * 2];
__device__ float g_z[BATCH * 768];
__device__ float g_h1[BATCH * 1024];
__device__ float g_h2[BATCH * 512];
__device__ float g_h3[BATCH * 128];

// ---------------- K0: Laplace filters + fused 18-tap weights ----------------
__global__ void k_setup(const float* __restrict__ la_a, const float* __restrict__ la_b) {
    __shared__ float sf[NCH * 16];
    int t = threadIdx.x; // 512
    {
        int c = t >> 4, k = t & 15;
        double tt = (double)k / 15.0;
        double p = tt - (double)la_b[c] / (double)la_a[c];
        double arg = 2.0 * M_PI * 50.0 * (p - 0.1);
        double coeff = 0.03 / sqrt(1.0 - 0.03 * 0.03);
        double y = 0.08 * exp(-coeff * arg) * (-sin(arg));
        sf[t] = (float)y;
        g_filt[t] = (float)y;
    }
    __syncthreads();
    for (int i = t; i < NCH * 18; i += 512) {
        int c = i / 18, j = i % 18;
        float s = 0.f;
        #pragma unroll
        for (int d = 0; d < 3; ++d) {
            int k = j - d;
            if (k >= 0 && k < 16) s += sf[c * 16 + k];
        }
        g_wbar[i] = s * (1.0f / 3.0f);
    }
}

// ---------------- K1: per-sample signal sum + autocorrelation ----------------
__global__ void __launch_bounds__(256) k_auto(const float* __restrict__ x) {
    __shared__ float xs[1040];
    __shared__ float red[8][17];
    int b = blockIdx.x, t = threadIdx.x;
    for (int j = t; j < 1040; j += 256) xs[j] = (j < LIN) ? x[b * LIN + j] : 0.f;
    __syncthreads();
    float acc[17];
    #pragma unroll
    for (int r = 0; r < 17; ++r) acc[r] = 0.f;
    for (int j = t; j < LIN; j += 256) {
        float xj = xs[j];
        acc[0] += xj;
        #pragma unroll
        for (int d = 0; d < 16; ++d) acc[1 + d] += xj * xs[j + d];
    }
    int lane = t & 31, w = t >> 5;
    #pragma unroll
    for (int r = 0; r < 17; ++r) {
        float v = acc[r];
        #pragma unroll
        for (int o = 16; o > 0; o >>= 1) v += __shfl_down_sync(0xffffffffu, v, o);
        if (lane == 0) red[w][r] = v;
    }
    __syncthreads();
    if (t < 17) {
        float s = 0.f;
        #pragma unroll
        for (int i = 0; i < 8; ++i) s += red[i][t];
        g_stats1[b * 17 + t] = s;
    }
}

// ---------------- K2: reduce stats, compute BN1 affine via filter autocorr ----------------
__global__ void __launch_bounds__(256) k_bn1b(const float* __restrict__ bn1_g,
                                              const float* __restrict__ bn1_b) {
    int t = threadIdx.x;
    double acc[17];
    #pragma unroll
    for (int r = 0; r < 17; ++r) acc[r] = 0.0;
    for (int b = t; b < BATCH; b += 256)
        #pragma unroll
        for (int r = 0; r < 17; ++r) acc[r] += (double)g_stats1[b * 17 + r];
    __shared__ double red[8];
    __shared__ double Cd[17];
    int lane = t & 31, w = t >> 5;
    for (int r = 0; r < 17; ++r) {
        double v = acc[r];
        #pragma unroll
        for (int o = 16; o > 0; o >>= 1) v += __shfl_down_sync(0xffffffffu, v, o);
        if (lane == 0) red[w] = v;
        __syncthreads();
        if (t == 0) {
            double s = 0.0;
            #pragma unroll
            for (int i = 0; i < 8; ++i) s += red[i];
            Cd[r] = s;
        }
        __syncthreads();
    }
    if (t < NCH) {
        int c = t;
        double f[16];
        #pragma unroll
        for (int k = 0; k < 16; ++k) f[k] = (double)g_filt[c * 16 + k];
        double W1 = 0.0;
        #pragma unroll
        for (int k = 0; k < 16; ++k) W1 += f[k];
        double E2 = 0.0;
        for (int d = 0; d < 16; ++d) {
            double A = 0.0;
            for (int k = 0; k + d < 16; ++k) A += f[k] * f[k + d];
            E2 += (d ? 2.0 : 1.0) * A * Cd[1 + d];
        }
        double N = (double)BATCH * (double)LCONV;
        double mean = Cd[0] * W1 / N;
        double var = E2 / N - mean * mean;
        double sc = (double)bn1_g[c] / sqrt(var + 1e-5);
        g_bn1s[c] = (float)sc;
        g_bn1t[c] = (float)((double)bn1_b[c] - sc * mean);
    }
}

// ---------------- K3: fused conv+avgpool+(BN folded)+both branches ----------------
__global__ void __launch_bounds__(256) k_fused(
    const float* __restrict__ x,
    const float* __restrict__ a1_w, const float* __restrict__ a1_b,
    const float* __restrict__ e1_w, const float* __restrict__ e1_b,
    const float* __restrict__ f1_w, const float* __restrict__ f1_b,
    const float* __restrict__ fa_w, const float* __restrict__ fa_b) {
    __shared__ __align__(16) float xe[528], xo[528];
    __shared__ __align__(16) float ue[8][264], uo[8][264];
    __shared__ __align__(16) float s1e[8][136], s1o[8][136];
    __shared__ __align__(16) float s2b[8][128];
    int b = blockIdx.x, t = threadIdx.x, w = t >> 5, lane = t & 31;
    const float* xb = x + (long)b * LIN;
    for (int i = t; i < 528; i += 256) {
        int p0 = 2 * i, p1 = 2 * i + 1;
        xe[i] = (p0 >= 16 && p0 < 1040) ? xb[p0 - 16] : 0.f;
        xo[i] = (p1 >= 16 && p1 < 1040) ? xb[p1 - 16] : 0.f;
    }
    __syncthreads();
    float* pue = ue[w]; float* puo = uo[w];
    float* p1e = s1e[w]; float* p1o = s1o[w];
    float* ps2 = s2b[w];

    for (int c = w; c < NCH; c += 8) {
        float wb[18];
        #pragma unroll
        for (int j = 0; j < 18; ++j) wb[j] = g_wbar[c * 18 + j];
        float sc = g_bn1s[c], sh = g_bn1t[c];
        // ---- u[520] = wbar conv (unnormalized pooled conv), even/odd split ----
        #pragma unroll
        for (int it = 0; it < 5; ++it) {
            int i0 = 4 * (lane + 32 * it);
            if (i0 < LH) {
                float e[12], o[12];
                *(float4*)&e[0] = *(const float4*)&xe[i0];
                *(float4*)&e[4] = *(const float4*)&xe[i0 + 4];
                *(float4*)&e[8] = *(const float4*)&xe[i0 + 8];
                *(float4*)&o[0] = *(const float4*)&xo[i0];
                *(float4*)&o[4] = *(const float4*)&xo[i0 + 4];
                *(float4*)&o[8] = *(const float4*)&xo[i0 + 8];
                float out[4];
                #pragma unroll
                for (int r = 0; r < 4; ++r) {
                    float s = 0.f;
                    #pragma unroll
                    for (int m = 0; m < 9; ++m)
                        s += e[r + m] * wb[2 * m] + o[r + m] * wb[2 * m + 1];
                    out[r] = s;
                }
                *(float2*)&pue[i0 >> 1] = make_float2(out[0], out[2]);
                *(float2*)&puo[i0 >> 1] = make_float2(out[1], out[3]);
            }
        }
        __syncwarp();
        #pragma unroll
        for (int br = 0; br < 2; ++br) {
            const float* w1p = br ? f1_w : a1_w;
            const float* b1p = br ? f1_b : a1_b;
            const float* w2p = br ? fa_w : e1_w;
            const float* b2p = br ? fa_b : e1_b;
            float wa2[8], wbv[8], Sw = 0.f, Sw2 = 0.f;
            #pragma unroll
            for (int k = 0; k < 8; ++k) {
                float v = w1p[c * 8 + k];
                Sw += v;
                wa2[k] = sc * v;                 // BN1 scale folded
                wbv[k] = w2p[c * 8 + k];
                Sw2 += wbv[k];
            }
            // branch0: always then eventually; branch1: eventually then always
            float beff1 = (br ? (1.f - b1p[c]) : (b1p[c] - Sw)) + sh * Sw;  // BN1 shift folded
            float beff2 = br ? (b2p[c] - Sw2) : (1.f - b2p[c]);
            // ---- stage1: 520 -> 257 ----
            #pragma unroll
            for (int it = 0; it < 3; ++it) {
                int n0 = 4 * (lane + 32 * it);
                if (n0 < L1) {
                    float e[8], o[8];
                    *(float4*)&e[0] = *(const float4*)&pue[n0];
                    *(float4*)&e[4] = *(const float4*)&pue[n0 + 4];
                    *(float4*)&o[0] = *(const float4*)&puo[n0];
                    *(float4*)&o[4] = *(const float4*)&puo[n0 + 4];
                    float out[4];
                    #pragma unroll
                    for (int r = 0; r < 4; ++r) {
                        float d = beff1;
                        #pragma unroll
                        for (int m = 0; m < 4; ++m)
                            d += e[r + m] * wa2[2 * m] + o[r + m] * wa2[2 * m + 1];
                        out[r] = d > 0.f ? d : 0.f;
                    }
                    if (n0 + 3 < L1) {
                        *(float2*)&p1e[n0 >> 1] = make_float2(out[0], out[2]);
                        *(float2*)&p1o[n0 >> 1] = make_float2(out[1], out[3]);
                    } else {
                        p1e[128] = out[0];       // n0 == 256
                    }
                }
            }
            __syncwarp();
            // ---- stage2: 257 -> 125 ----
            {
                int n0 = 4 * lane; // 0..124
                float e[8], o[8];
                *(float4*)&e[0] = *(const float4*)&p1e[n0];
                *(float4*)&e[4] = *(const float4*)&p1e[n0 + 4];
                *(float4*)&o[0] = *(const float4*)&p1o[n0];
                *(float4*)&o[4] = *(const float4*)&p1o[n0 + 4];
                float out[4];
                #pragma unroll
                for (int r = 0; r < 4; ++r) {
                    float d = beff2;
                    #pragma unroll
                    for (int m = 0; m < 4; ++m)
                        d += e[r + m] * wbv[2 * m] + o[r + m] * wbv[2 * m + 1];
                    out[r] = d > 0.f ? d : 0.f;
                }
                #pragma unroll
                for (int r = 0; r < 4; ++r)
                    if (n0 + r < L2) ps2[n0 + r] = out[r];
            }
            __syncwarp();
            // ---- maxpool(4,4) + BN partials ----
            float mv = 0.f;
            if (lane < LM) {
                mv = ps2[4 * lane];
                #pragma unroll
                for (int j = 1; j < 4; ++j) mv = fmaxf(mv, ps2[4 * lane + j]);
                float* mo = (br ? g_m2 : g_m1) + ((long)b * NCH + c) * LM;
                mo[lane] = mv;
            }
            float s = (lane < LM) ? mv : 0.f;
            float q = s * mv;
            #pragma unroll
            for (int o2 = 16; o2 > 0; o2 >>= 1) {
                s += __shfl_down_sync(0xffffffffu, s, o2);
                q += __shfl_down_sync(0xffffffffu, q, o2);
            }
            if (lane == 0) {
                g_p2sum[(br * NCH + c) * BATCH + b] = s;
                g_p2sq[(br * NCH + c) * BATCH + b] = q;
            }
            __syncwarp();
        }
    }
}

// ---------------- K5: BN2/BN3 folded into final eventually ----------------
__global__ void __launch_bounds__(256) k_bn23(
    const float* __restrict__ bn2_g, const float* __restrict__ bn2_b,
    const float* __restrict__ e2_w, const float* __restrict__ e2_b,
    const float* __restrict__ bn3_g, const float* __restrict__ bn3_b,
    const float* __restrict__ f2_w, const float* __restrict__ f2_b) {
    int idx = blockIdx.x;  // br*32 + c
    int br = idx >> 5, c = idx & 31;
    int t = threadIdx.x;
    double s = 0.0, q = 0.0;
    for (int b = t; b < BATCH; b += 256) {
        s += (double)g_p2sum[idx * BATCH + b];
        q += (double)g_p2sq[idx * BATCH + b];
    }
    __shared__ double rs[8], rq[8];
    int lane = t & 31, w = t >> 5;
    #pragma unroll
    for (int o = 16; o > 0; o >>= 1) {
        s += __shfl_down_sync(0xffffffffu, s, o);
        q += __shfl_down_sync(0xffffffffu, q, o);
    }
    if (lane == 0) { rs[w] = s; rq[w] = q; }
    __syncthreads();
    if (t == 0) {
        double S = 0.0, Q = 0.0;
        #pragma unroll
        for (int i = 0; i < 8; ++i) { S += rs[i]; Q += rq[i]; }
        double N = (double)BATCH * (double)LM;
        double mean = S / N;
        double var = Q / N - mean * mean;
        const float* gg = br ? bn3_g : bn2_g;
        const float* gb = br ? bn3_b : bn2_b;
        const float* wp = br ? f2_w : e2_w;
        const float* bp = br ? f2_b : e2_b;
        double sc2 = (double)gg[c] / sqrt(var + 1e-5);
        double tt = (double)gb[c] - sc2 * mean;
        double sumw = 0.0;
        for (int k = 0; k < 8; ++k) sumw += (double)wp[c * 8 + k];
        g_eff[idx * 2 + 0] = (float)sc2;
        g_eff[idx * 2 + 1] = (float)(1.0 - (double)bp[c] + tt * sumw);
    }
}

// ---------------- K6: final eventually + concat -> g_z ----------------
__global__ void __launch_bounds__(256) k_e2z(const float* __restrict__ e2_w,
                                             const float* __restrict__ f2_w) {
    __shared__ float sm[2 * NCH * LM];
    int b = blockIdx.x, t = threadIdx.x;
    for (int i = t; i < NCH * LM; i += 256) {
        sm[i] = g_m1[(long)b * NCH * LM + i];
        sm[NCH * LM + i] = g_m2[(long)b * NCH * LM + i];
    }
    __syncthreads();
    #pragma unroll
    for (int r = 0; r < 3; ++r) {
        int o = t + 256 * r;
        int br = o / 384;
        int rem = o - br * 384;
        int c = rem / LE, n = rem - c * LE;
        const float* wp = br ? f2_w : e2_w;
        float alpha = g_eff[(br * NCH + c) * 2 + 0];
        float beta  = g_eff[(br * NCH + c) * 2 + 1];
        const float* m = sm + br * (NCH * LM) + c * LM + 2 * n;
        float d = 0.f;
        #pragma unroll
        for (int k = 0; k < 8; ++k) d += m[k] * wp[c * 8 + k];
        float v = beta + alpha * d;
        g_z[(long)b * 768 + o] = v > 0.f ? v : 0.f;
    }
}

// ---------------- GEMM 128x64 tile, BK=8: C = relu(A@W + bias) ----------------
__global__ void __launch_bounds__(256) k_gemm128(
    const float* __restrict__ A, const float* __restrict__ W,
    const float* __restrict__ bias, float* __restrict__ C,
    int M, int N, int K) {
    __shared__ float As[8][128];
    __shared__ float Ws[8][64];
    int tid = threadIdx.x;
    int row0 = blockIdx.y * 128, col0 = blockIdx.x * 64;
    int tx = tid & 15, ty = tid >> 4;
    int ar = tid >> 1, aq = (tid & 1) * 4;
    float acc[8][4] = {};
    for (int k0 = 0; k0 < K; k0 += 8) {
        float4 a4 = *(const float4*)&A[(long)(row0 + ar) * K + k0 + aq];
        As[aq + 0][ar] = a4.x;
        As[aq + 1][ar] = a4.y;
        As[aq + 2][ar] = a4.z;
        As[aq + 3][ar] = a4.w;
        #pragma unroll
        for (int i = 0; i < 2; ++i) {
            int e = tid + 256 * i;
            int kk = e >> 6, n = e & 63;
            Ws[kk][n] = W[(long)(k0 + kk) * N + col0 + n];
        }
        __syncthreads();
        #pragma unroll
        for (int kk = 0; kk < 8; ++kk) {
            float a[8], wv[4];
            *(float4*)&a[0] = *(const float4*)&As[kk][ty * 8];
            *(float4*)&a[4] = *(const float4*)&As[kk][ty * 8 + 4];
            *(float4*)wv = *(const float4*)&Ws[kk][tx * 4];
            #pragma unroll
            for (int i = 0; i < 8; ++i)
                #pragma unroll
                for (int j = 0; j < 4; ++j) acc[i][j] += a[i] * wv[j];
        }
        __syncthreads();
    }
    #pragma unroll
    for (int i = 0; i < 8; ++i) {
        int m = row0 + ty * 8 + i;
        #pragma unroll
        for (int j = 0; j < 4; ++j) {
            int n = col0 + tx * 4 + j;
            float v = acc[i][j] + bias[n];
            C[(long)m * N + n] = v > 0.f ? v : 0.f;
        }
    }
}

// ---------------- GEMM 64x64 tile (for small N) ----------------
__global__ void __launch_bounds__(256) k_gemm_relu(
    const float* __restrict__ A, const float* __restrict__ W,
    const float* __restrict__ bias, float* __restrict__ C,
    int M, int N, int K) {
    __shared__ float As[8][64];
    __shared__ float Ws[8][64];
    int tid = threadIdx.x;
    int tx = tid & 15, ty = tid >> 4;
    int row0 = blockIdx.y * 64, col0 = blockIdx.x * 64;
    float acc[4][4] = {};
    for (int k0 = 0; k0 < K; k0 += 8) {
        #pragma unroll
        for (int i = 0; i < 2; ++i) {
            int e = tid + 256 * i;
            int r = e >> 3, kk = e & 7;
            As[kk][r] = A[(long)(row0 + r) * K + k0 + kk];
        }
        #pragma unroll
        for (int i = 0; i < 2; ++i) {
            int e = tid + 256 * i;
            int kk = e >> 6, n = e & 63;
            Ws[kk][n] = W[(long)(k0 + kk) * N + col0 + n];
        }
        __syncthreads();
        #pragma unroll
        for (int kk = 0; kk < 8; ++kk) {
            float a[4], wv[4];
            *(float4*)a = *(const float4*)&As[kk][ty * 4];
            *(float4*)wv = *(const float4*)&Ws[kk][tx * 4];
            #pragma unroll
            for (int i = 0; i < 4; ++i)
                #pragma unroll
                for (int j = 0; j < 4; ++j) acc[i][j] += a[i] * wv[j];
        }
        __syncthreads();
    }
    #pragma unroll
    for (int i = 0; i < 4; ++i) {
        int m = row0 + ty * 4 + i;
        #pragma unroll
        for (int j = 0; j < 4; ++j) {
            int n = col0 + tx * 4 + j;
            float v = acc[i][j] + bias[n];
            C[(long)m * N + n] = v > 0.f ? v : 0.f;
        }
    }
}

// ---------------- final 128->10 layer ----------------
__global__ void __launch_bounds__(256) k_fc4(const float* __restrict__ w4,
                                             const float* __restrict__ b4,
                                             float* __restrict__ out) {
    int g = blockIdx.x * 256 + threadIdx.x;
    if (g >= BATCH * 10) return;
    int b = g / 10, j = g - b * 10;
    const float* h = g_h3 + (long)b * 128;
    float acc = b4[j];
    #pragma unroll 16
    for (int k = 0; k < 128; ++k) acc += h[k] * w4[k * 10 + j];
    out[g] = acc > 0.f ? acc : 0.f;
}

// ---------------- launcher ----------------
extern "C" void kernel_launch(void* const* d_in, const int* in_sizes, int n_in,
                              void* d_out, int out_size) {
    (void)in_sizes; (void)n_in; (void)out_size;
    const float* x      = (const float*)d_in[0];
    const float* la_a   = (const float*)d_in[1];
    const float* la_b   = (const float*)d_in[2];
    // d_in[3] la_bias cancels under BN1
    const float* bn1_g  = (const float*)d_in[4];
    const float* bn1_b  = (const float*)d_in[5];
    const float* a1_w   = (const float*)d_in[6];
    const float* a1_b   = (const float*)d_in[7];
    const float* e1_w   = (const float*)d_in[8];
    const float* e1_b   = (const float*)d_in[9];
    const float* bn2_g  = (const float*)d_in[10];
    const float* bn2_b  = (const float*)d_in[11];
    const float* e2_w   = (const float*)d_in[12];
    const float* e2_b   = (const float*)d_in[13];
    const float* f1_w   = (const float*)d_in[14];
    const float* f1_b   = (const float*)d_in[15];
    const float* fa_w   = (const float*)d_in[16];
    const float* fa_b   = (const float*)d_in[17];
    const float* bn3_g  = (const float*)d_in[18];
    const float* bn3_b  = (const float*)d_in[19];
    const float* f2_w   = (const float*)d_in[20];
    const float* f2_b   = (const float*)d_in[21];
    const float* w1     = (const float*)d_in[22];
    const float* b1     = (const float*)d_in[23];
    const float* w2     = (const float*)d_in[24];
    const float* b2     = (const float*)d_in[25];
    const float* w3     = (const float*)d_in[26];
    const float* b3     = (const float*)d_in[27];
    const float* w4     = (const float*)d_in[28];
    const float* b4     = (const float*)d_in[29];
    float* out = (float*)d_out;

    float *p_z, *p_h1, *p_h2, *p_h3;
    cudaGetSymbolAddress((void**)&p_z, g_z);
    cudaGetSymbolAddress((void**)&p_h1, g_h1);
    cudaGetSymbolAddress((void**)&p_h2, g_h2);
    cudaGetSymbolAddress((void**)&p_h3, g_h3);

    k_setup<<<1, 512>>>(la_a, la_b);
    k_auto<<<BATCH, 256>>>(x);
    k_bn1b<<<1, 256>>>(bn1_g, bn1_b);
    k_fused<<<BATCH, 256>>>(x, a1_w, a1_b, e1_w, e1_b, f1_w, f1_b, fa_w, fa_b);
    k_bn23<<<64, 256>>>(bn2_g, bn2_b, e2_w, e2_b, bn3_g, bn3_b, f2_w, f2_b);
    k_e2z<<<BATCH, 256>>>(e2_w, f2_w);
    k_gemm128<<<dim3(1024 / 64, 1024 / 128), 256>>>(p_z, w1, b1, p_h1, BATCH, 1024, 768);
    k_gemm128<<<dim3(512 / 64, 1024 / 128), 256>>>(p_h1, w2, b2, p_h2, BATCH, 512, 1024);
    k_gemm_relu<<<dim3(128 / 64, 1024 / 64), 256>>>(p_h2, w3, b3, p_h3, BATCH, 128, 512);
    k_fc4<<<(BATCH * 10 + 255) / 256, 256>>>(w4, b4, out);
}